// round 1
// baseline (speedup 1.0000x reference)
#include <cuda_runtime.h>
#include <cstdint>
#include <cstddef>

// Problem constants
#define B_    256
#define P_    196
#define E_    2048
#define A_    512
#define MTOT  (B_*P_)      // 50176

// GEMM tiling
#define MT 128
#define NT 256
#define KC 32
#define NKC (E_/KC)        // 64

// Scratch (no allocations allowed)
__device__ float g_att2[B_*A_];   // dh@Wd + Wd_b + We_b  (combined bias per (b,a))
__device__ float g_att [MTOT];    // logits (pre-softmax)

// ---------------- helpers ----------------
__device__ __forceinline__ void cp_async16(float* smem_dst, const float* gmem_src){
    unsigned s = (unsigned)__cvta_generic_to_shared(smem_dst);
    asm volatile("cp.async.cg.shared.global [%0], [%1], 16;\n" :: "r"(s), "l"(gmem_src));
}
__device__ __forceinline__ unsigned f2tf(float f){
    unsigned u; asm("cvt.rna.tf32.f32 %0, %1;\n" : "=r"(u) : "f"(f)); return u;
}
__device__ __forceinline__ void mma_tf32(float c[4], const unsigned a[4], unsigned b0, unsigned b1){
    asm volatile(
        "mma.sync.aligned.m16n8k8.row.col.f32.tf32.tf32.f32 "
        "{%0,%1,%2,%3}, {%4,%5,%6,%7}, {%8,%9}, {%0,%1,%2,%3};\n"
        : "+f"(c[0]), "+f"(c[1]), "+f"(c[2]), "+f"(c[3])
        : "r"(a[0]), "r"(a[1]), "r"(a[2]), "r"(a[3]), "r"(b0), "r"(b1));
}

// ---------------- kernel 1: att2/bias + zero logits ----------------
// grid 32, block 128. Each block handles 8 batch rows. Also zeroes g_att.
__global__ void att2_kernel(const float* __restrict__ dh,  const float* __restrict__ Wd,
                            const float* __restrict__ Wdb, const float* __restrict__ Web){
    __shared__ float dh_s[8][512];
    const int tid = threadIdx.x;
    const int bb  = blockIdx.x * 8;
    for (int i = tid; i < 8*512; i += 128)
        dh_s[i >> 9][i & 511] = dh[(size_t)bb*512 + i];
    for (int i = blockIdx.x*128 + tid; i < MTOT; i += 32*128)
        g_att[i] = 0.f;
    __syncthreads();

    float acc[8][4];
    #pragma unroll
    for (int j = 0; j < 4; j++){
        float base = Wdb[tid + j*128] + Web[tid + j*128];
        #pragma unroll
        for (int q = 0; q < 8; q++) acc[q][j] = base;
    }
    for (int k = 0; k < 512; k++){
        #pragma unroll
        for (int j = 0; j < 4; j++){
            float w = Wd[(size_t)k*512 + tid + j*128];
            #pragma unroll
            for (int q = 0; q < 8; q++) acc[q][j] += dh_s[q][k] * w;
        }
    }
    #pragma unroll
    for (int q = 0; q < 8; q++)
        #pragma unroll
        for (int j = 0; j < 4; j++)
            g_att2[(size_t)(bb+q)*512 + tid + j*128] = acc[q][j];
}

// ---------------- kernel 2: fused TF32 GEMM + relu + Wf-dot -> logits ----------------
// grid = (MTOT/MT)*2 = 784, block 512.  m0 = (bid>>1)*128, n0 = (bid&1)*256.
// smem layout (floats): As[2][128][36] | Bs[2][32][264] | bias[2][512] | wf[512] | satt[128]
#define AS_SZ   (2*128*36)    // 9216
#define BS_SZ   (2*32*264)    // 16896
#define SMEM_FLOATS (AS_SZ + BS_SZ + 1024 + 512 + 128)   // 27776
#define SMEM_BYTES  (SMEM_FLOATS*4)                      // 111104

__device__ __forceinline__ void load_chunk(const float* __restrict__ enc,
                                           const float* __restrict__ We,
                                           float* As, float* Bs,
                                           int m0, int n0, int kc, int buf, int tid){
    const float* Ag = enc + (size_t)m0*E_ + kc*KC;
    float* Ab = As + buf*(128*36);
    #pragma unroll
    for (int i = 0; i < 2; i++){
        int idx = tid + i*512;
        int r = idx >> 3, seg = idx & 7;                     // 128 rows x 8 float4
        cp_async16(Ab + r*36 + seg*4, Ag + (size_t)r*E_ + seg*4);
    }
    const float* Bg = We + (size_t)(kc*KC)*A_ + n0;
    float* Bb = Bs + buf*(32*264);
    #pragma unroll
    for (int i = 0; i < 4; i++){
        int idx = tid + i*512;
        int kk = idx >> 6, seg = idx & 63;                   // 32 rows x 64 float4
        cp_async16(Bb + kk*264 + seg*4, Bg + (size_t)kk*A_ + seg*4);
    }
    asm volatile("cp.async.commit_group;\n");
}

__global__ void __launch_bounds__(512, 1)
gemm_att_kernel(const float* __restrict__ enc, const float* __restrict__ We,
                const float* __restrict__ Wf){
    extern __shared__ float sm[];
    float* As     = sm;
    float* Bs     = sm + AS_SZ;
    float* bias_s = Bs + BS_SZ;          // [2][512]
    float* wf_s   = bias_s + 1024;       // [512]
    float* satt   = wf_s + 512;          // [128]

    const int tid = threadIdx.x;
    const int bid = blockIdx.x;
    const int m0  = (bid >> 1) * MT;
    const int n0  = (bid & 1)  * NT;
    const int b_first = m0 / P_;

    // prologue: biases + wf + zero partial logits
    {
        int i = tid;                     // 512 threads, one each
        wf_s[i]       = Wf[i];
        bias_s[i]     = g_att2[(size_t)b_first*512 + i];
        bias_s[512+i] = (b_first + 1 < B_) ? g_att2[(size_t)(b_first+1)*512 + i] : 0.f;
    }
    if (tid < 128) satt[tid] = 0.f;

    const int warp = tid >> 5, lane = tid & 31;
    const int wm = warp >> 2, wn = warp & 3;        // 4x4 warp grid; warp tile 32x64
    const int g = lane >> 2, t = lane & 3;

    float c[2][8][4];
    #pragma unroll
    for (int mi = 0; mi < 2; mi++)
        #pragma unroll
        for (int ni = 0; ni < 8; ni++)
            #pragma unroll
            for (int j = 0; j < 4; j++) c[mi][ni][j] = 0.f;

    load_chunk(enc, We, As, Bs, m0, n0, 0, 0, tid);

    for (int kc = 0; kc < NKC; kc++){
        const int buf = kc & 1;
        if (kc < NKC-1){
            load_chunk(enc, We, As, Bs, m0, n0, kc+1, buf^1, tid);
            asm volatile("cp.async.wait_group 1;\n");
        } else {
            asm volatile("cp.async.wait_group 0;\n");
        }
        __syncthreads();

        const float* Abase = As + buf*(128*36) + (wm*32)*36;
        const float* Bbase = Bs + buf*(32*264) + wn*64;
        #pragma unroll
        for (int ks = 0; ks < 4; ks++){
            unsigned a[2][4];
            #pragma unroll
            for (int mi = 0; mi < 2; mi++){
                const float* ap = Abase + (mi*16 + g)*36 + ks*8 + t;
                a[mi][0] = f2tf(ap[0]);
                a[mi][1] = f2tf(ap[8*36]);
                a[mi][2] = f2tf(ap[4]);
                a[mi][3] = f2tf(ap[8*36 + 4]);
            }
            #pragma unroll
            for (int ni = 0; ni < 8; ni++){
                const float* bp = Bbase + (ks*8 + t)*264 + ni*8 + g;
                unsigned b0 = f2tf(bp[0]);
                unsigned b1 = f2tf(bp[4*264]);
                mma_tf32(c[0][ni], a[0], b0, b1);
                mma_tf32(c[1][ni], a[1], b0, b1);
            }
        }
        __syncthreads();
    }

    // epilogue: h = relu(acc + bias(b_row, col)); att += h .* Wf
    float attr[2][2] = {{0.f,0.f},{0.f,0.f}};
    #pragma unroll
    for (int ni = 0; ni < 8; ni++){
        const int colg = n0 + wn*64 + ni*8 + 2*t;
        const float w0 = wf_s[colg], w1 = wf_s[colg+1];
        #pragma unroll
        for (int mi = 0; mi < 2; mi++){
            #pragma unroll
            for (int rr = 0; rr < 2; rr++){
                const int rowg = m0 + wm*32 + mi*16 + g + rr*8;
                const int rb   = rowg / P_ - b_first;          // 0 or 1
                const float bv0 = bias_s[rb*512 + colg];
                const float bv1 = bias_s[rb*512 + colg + 1];
                const float h0 = fmaxf(c[mi][ni][rr*2+0] + bv0, 0.f);
                const float h1 = fmaxf(c[mi][ni][rr*2+1] + bv1, 0.f);
                attr[mi][rr] += h0*w0 + h1*w1;
            }
        }
    }
    #pragma unroll
    for (int mi = 0; mi < 2; mi++)
        #pragma unroll
        for (int rr = 0; rr < 2; rr++){
            float v = attr[mi][rr];
            v += __shfl_xor_sync(0xffffffffu, v, 1);
            v += __shfl_xor_sync(0xffffffffu, v, 2);
            if (t == 0) atomicAdd(&satt[wm*32 + mi*16 + g + rr*8], v);
        }
    __syncthreads();
    if (tid < 128) atomicAdd(&g_att[m0 + tid], satt[tid]);
}

// ---------------- kernel 3: softmax over P per batch row ----------------
__global__ void softmax_kernel(float* __restrict__ alpha_out){
    const int b = blockIdx.x, tid = threadIdx.x;    // 256 threads
    __shared__ float red[256];
    float v = (tid < P_) ? g_att[b*P_ + tid] : -1e30f;
    red[tid] = v; __syncthreads();
    for (int s = 128; s > 0; s >>= 1){
        if (tid < s) red[tid] = fmaxf(red[tid], red[tid+s]);
        __syncthreads();
    }
    const float mx = red[0]; __syncthreads();
    const float e = (tid < P_) ? expf(v - mx) : 0.f;
    red[tid] = e; __syncthreads();
    for (int s = 128; s > 0; s >>= 1){
        if (tid < s) red[tid] += red[tid+s];
        __syncthreads();
    }
    const float inv = 1.f / red[0];
    if (tid < P_) alpha_out[b*P_ + tid] = e * inv;
}

// ---------------- kernel 4: awe[b,e] = sum_p enc[b,p,e] * alpha[b,p] ----------------
__global__ void __launch_bounds__(512)
awe_kernel(const float4* __restrict__ enc4, const float* __restrict__ alpha,
           float4* __restrict__ out4){
    const int b = blockIdx.x, tid = threadIdx.x;    // 512 threads, one float4 column each
    __shared__ float al[P_];
    if (tid < P_) al[tid] = alpha[b*P_ + tid];
    __syncthreads();
    float4 acc = make_float4(0.f, 0.f, 0.f, 0.f);
    const float4* ep = enc4 + (size_t)b * P_ * (E_/4) + tid;
    #pragma unroll 4
    for (int p = 0; p < P_; p++){
        const float a = al[p];
        const float4 v = ep[(size_t)p * (E_/4)];
        acc.x += a*v.x; acc.y += a*v.y; acc.z += a*v.z; acc.w += a*v.w;
    }
    out4[(size_t)b * (E_/4) + tid] = acc;
}

// ---------------- launch ----------------
extern "C" void kernel_launch(void* const* d_in, const int* in_sizes, int n_in,
                              void* d_out, int out_size){
    const float* enc  = (const float*)d_in[0];   // (B,P,E)
    const float* dh   = (const float*)d_in[1];   // (1,B,D)
    const float* We_w = (const float*)d_in[2];   // (E,A)
    const float* We_b = (const float*)d_in[3];   // (A)
    const float* Wd_w = (const float*)d_in[4];   // (D,A)
    const float* Wd_b = (const float*)d_in[5];   // (A)
    const float* Wf_w = (const float*)d_in[6];   // (A)
    // d_in[7] = Wf_b: scalar logit shift -> softmax-invariant, outputs don't depend on it.

    float* out       = (float*)d_out;
    float* awe_out   = out;                       // (B,E) = 524288 floats
    float* alpha_out = out + (size_t)B_*E_;       // (B,P) =  50176 floats

    cudaFuncSetAttribute(gemm_att_kernel, cudaFuncAttributeMaxDynamicSharedMemorySize, SMEM_BYTES);

    att2_kernel   <<<32, 128>>>(dh, Wd_w, Wd_b, We_b);
    gemm_att_kernel<<<(MTOT/MT)*2, 512, SMEM_BYTES>>>(enc, We_w, Wf_w);
    softmax_kernel<<<B_, 256>>>(alpha_out);
    awe_kernel    <<<B_, 512>>>((const float4*)enc, alpha_out, (float4*)awe_out);
}

// round 3
// speedup vs baseline: 1.3792x; 1.3792x over previous
#include <cuda_runtime.h>
#include <cuda_fp16.h>
#include <cstdint>
#include <cstddef>

#define B_    256
#define P_    196
#define E_    2048
#define A_    512
#define MTOT  (B_*P_)      // 50176

// GEMM tiling
#define MT 128
#define NT 256
#define KC 64
#define NKC (E_/KC)        // 32

// scratch (static device arrays only — no runtime allocation)
__device__ float  g_att2[B_*A_];   // dh@Wd + Wd_b + We_b combined bias
__device__ float  g_att [MTOT];    // logits
__device__ __half g_Bth [A_*E_];   // We transposed to [N][K], fp16 (2MB)

// ---------------- helpers ----------------
__device__ __forceinline__ void cp_async16(void* smem_dst, const void* gmem_src){
    unsigned s = (unsigned)__cvta_generic_to_shared(smem_dst);
    asm volatile("cp.async.cg.shared.global [%0], [%1], 16;\n" :: "r"(s), "l"(gmem_src));
}
__device__ __forceinline__ uint32_t packh(float2 v){
    __half2 h = __float22half2_rn(v);
    return *reinterpret_cast<uint32_t*>(&h);
}
__device__ __forceinline__ void mma_fp16(float c[4], uint32_t a0, uint32_t a1, uint32_t a2, uint32_t a3,
                                         uint32_t b0, uint32_t b1){
    asm volatile(
        "mma.sync.aligned.m16n8k16.row.col.f32.f16.f16.f32 "
        "{%0,%1,%2,%3}, {%4,%5,%6,%7}, {%8,%9}, {%0,%1,%2,%3};\n"
        : "+f"(c[0]), "+f"(c[1]), "+f"(c[2]), "+f"(c[3])
        : "r"(a0), "r"(a1), "r"(a2), "r"(a3), "r"(b0), "r"(b1));
}

// ---------------- kernel 0: g_Bth[n][k] = fp16(We[k][n]) ----------------
__global__ void prep_bh(const float* __restrict__ We){
    __shared__ float t[32][33];
    const int k0 = blockIdx.x*32, n0 = blockIdx.y*32;
    const int tx = threadIdx.x, ty = threadIdx.y;   // (32,8)
    #pragma unroll
    for (int i = 0; i < 4; i++)
        t[ty + i*8][tx] = We[(size_t)(k0 + ty + i*8)*A_ + n0 + tx];
    __syncthreads();
    #pragma unroll
    for (int i = 0; i < 4; i++)
        g_Bth[(size_t)(n0 + ty + i*8)*E_ + k0 + tx] = __float2half_rn(t[tx][ty + i*8]);
}

// ---------------- kernel 1: att2/bias + zero logits ----------------
__global__ void att2_kernel(const float* __restrict__ dh,  const float* __restrict__ Wd,
                            const float* __restrict__ Wdb, const float* __restrict__ Web){
    __shared__ float dh_s[8][512];
    const int tid = threadIdx.x;
    const int bb  = blockIdx.x * 8;
    for (int i = tid; i < 8*512; i += 128)
        dh_s[i >> 9][i & 511] = dh[(size_t)bb*512 + i];
    for (int i = blockIdx.x*128 + tid; i < MTOT; i += 32*128)
        g_att[i] = 0.f;
    __syncthreads();

    float acc[8][4];
    #pragma unroll
    for (int j = 0; j < 4; j++){
        float base = Wdb[tid + j*128] + Web[tid + j*128];
        #pragma unroll
        for (int q = 0; q < 8; q++) acc[q][j] = base;
    }
    for (int k = 0; k < 512; k++){
        #pragma unroll
        for (int j = 0; j < 4; j++){
            float w = Wd[(size_t)k*512 + tid + j*128];
            #pragma unroll
            for (int q = 0; q < 8; q++) acc[q][j] += dh_s[q][k] * w;
        }
    }
    #pragma unroll
    for (int q = 0; q < 8; q++)
        #pragma unroll
        for (int j = 0; j < 4; j++)
            g_att2[(size_t)(bb+q)*512 + tid + j*128] = acc[q][j];
}

// ---------------- kernel 2: fused FP16 mma GEMM + relu + Wf-dot -> logits ----------------
// grid = (MTOT/MT)*2 = 784, block 512.  m0 = (bid>>1)*128, n0 = (bid&1)*256.
// smem: As[2][128][68] f32 | Bs[2][256][72] half | bias[2][512] | wf[512] | satt[128]
#define AS_STRIDE 68
#define BS_STRIDE 72
#define AS_FLOATS (2*128*AS_STRIDE)                 // 17408
#define BS_HALVES (2*256*BS_STRIDE)                 // 36864
#define EX_FLOATS (1024 + 512 + 128)
#define SMEM_BYTES (AS_FLOATS*4 + BS_HALVES*2 + EX_FLOATS*4)   // 150016

__device__ __forceinline__ void load_chunk(const float* __restrict__ enc,
                                           float* As, __half* Bs,
                                           int m0, int n0, int kc, int buf, int tid){
    const float* Ag = enc + (size_t)m0*E_ + kc*KC;
    float* Ab = As + buf*(128*AS_STRIDE);
    #pragma unroll
    for (int i = 0; i < 4; i++){
        int idx = tid + i*512;
        int r = idx >> 4, seg = idx & 15;                 // 128 rows x 16 float4
        cp_async16(Ab + r*AS_STRIDE + seg*4, Ag + (size_t)r*E_ + seg*4);
    }
    const __half* Bg = g_Bth + (size_t)n0*E_ + kc*KC;
    __half* Bb = Bs + buf*(256*BS_STRIDE);
    #pragma unroll
    for (int i = 0; i < 4; i++){
        int idx = tid + i*512;
        int n = idx >> 3, seg = idx & 7;                  // 256 rows x 8 chunks of 8 halves
        cp_async16(Bb + n*BS_STRIDE + seg*8, Bg + (size_t)n*E_ + seg*8);
    }
    asm volatile("cp.async.commit_group;\n");
}

__global__ void __launch_bounds__(512, 1)
gemm_att_kernel(const float* __restrict__ enc, const float* __restrict__ Wf){
    extern __shared__ char smraw[];
    float*  As     = (float*)smraw;
    __half* Bs     = (__half*)(smraw + AS_FLOATS*4);
    float*  bias_s = (float*)(smraw + AS_FLOATS*4 + BS_HALVES*2);   // [2][512]
    float*  wf_s   = bias_s + 1024;
    float*  satt   = wf_s + 512;

    const int tid = threadIdx.x;
    const int bid = blockIdx.x;
    const int m0  = (bid >> 1) * MT;
    const int n0  = (bid & 1)  * NT;
    const int b_first = m0 / P_;

    {
        int i = tid;
        wf_s[i]       = Wf[i];
        bias_s[i]     = g_att2[(size_t)b_first*512 + i];
        bias_s[512+i] = (b_first + 1 < B_) ? g_att2[(size_t)(b_first+1)*512 + i] : 0.f;
    }
    if (tid < 128) satt[tid] = 0.f;

    const int warp = tid >> 5, lane = tid & 31;
    const int wm = warp >> 2, wn = warp & 3;        // 4x4 warp grid; warp tile 32x64
    const int g = lane >> 2, t = lane & 3;

    float c[2][8][4];
    #pragma unroll
    for (int mi = 0; mi < 2; mi++)
        #pragma unroll
        for (int ni = 0; ni < 8; ni++)
            #pragma unroll
            for (int j = 0; j < 4; j++) c[mi][ni][j] = 0.f;

    load_chunk(enc, As, Bs, m0, n0, 0, 0, tid);

    for (int kc = 0; kc < NKC; kc++){
        const int buf = kc & 1;
        if (kc < NKC-1){
            load_chunk(enc, As, Bs, m0, n0, kc+1, buf^1, tid);
            asm volatile("cp.async.wait_group 1;\n");
        } else {
            asm volatile("cp.async.wait_group 0;\n");
        }
        __syncthreads();

        const float*  Abase = As + buf*(128*AS_STRIDE) + (wm*32)*AS_STRIDE;
        const __half* Bbase = Bs + buf*(256*BS_STRIDE) + (wn*64)*BS_STRIDE;
        #pragma unroll
        for (int ks = 0; ks < 4; ks++){                  // 4 x k16
            uint32_t a[2][4];
            #pragma unroll
            for (int mi = 0; mi < 2; mi++){
                const float* ap = Abase + (mi*16 + g)*AS_STRIDE + ks*16 + 2*t;
                a[mi][0] = packh(*(const float2*)(ap));
                a[mi][1] = packh(*(const float2*)(ap + 8*AS_STRIDE));
                a[mi][2] = packh(*(const float2*)(ap + 8));
                a[mi][3] = packh(*(const float2*)(ap + 8*AS_STRIDE + 8));
            }
            #pragma unroll
            for (int ni = 0; ni < 8; ni++){
                const __half* bp = Bbase + (ni*8 + g)*BS_STRIDE + ks*16 + 2*t;
                uint32_t b0 = *(const uint32_t*)(bp);
                uint32_t b1 = *(const uint32_t*)(bp + 8);
                mma_fp16(c[0][ni], a[0][0], a[0][1], a[0][2], a[0][3], b0, b1);
                mma_fp16(c[1][ni], a[1][0], a[1][1], a[1][2], a[1][3], b0, b1);
            }
        }
        __syncthreads();
    }

    // epilogue: h = relu(acc + bias(b_row, col)); att += h .* Wf
    float attr[2][2] = {{0.f,0.f},{0.f,0.f}};
    #pragma unroll
    for (int ni = 0; ni < 8; ni++){
        const int colg = n0 + wn*64 + ni*8 + 2*t;
        const float w0 = wf_s[colg], w1 = wf_s[colg+1];
        #pragma unroll
        for (int mi = 0; mi < 2; mi++){
            #pragma unroll
            for (int rr = 0; rr < 2; rr++){
                const int rowg = m0 + wm*32 + mi*16 + g + rr*8;
                const int rb   = rowg / P_ - b_first;          // 0 or 1
                const float bv0 = bias_s[rb*512 + colg];
                const float bv1 = bias_s[rb*512 + colg + 1];
                const float h0 = fmaxf(c[mi][ni][rr*2+0] + bv0, 0.f);
                const float h1 = fmaxf(c[mi][ni][rr*2+1] + bv1, 0.f);
                attr[mi][rr] += h0*w0 + h1*w1;
            }
        }
    }
    #pragma unroll
    for (int mi = 0; mi < 2; mi++)
        #pragma unroll
        for (int rr = 0; rr < 2; rr++){
            float v = attr[mi][rr];
            v += __shfl_xor_sync(0xffffffffu, v, 1);
            v += __shfl_xor_sync(0xffffffffu, v, 2);
            if (t == 0) atomicAdd(&satt[wm*32 + mi*16 + g + rr*8], v);
        }
    __syncthreads();
    if (tid < 128) atomicAdd(&g_att[m0 + tid], satt[tid]);
}

// ---------------- kernel 3: softmax over P per batch row ----------------
__global__ void softmax_kernel(float* __restrict__ alpha_out){
    const int b = blockIdx.x, tid = threadIdx.x;    // 256 threads
    __shared__ float red[256];
    float v = (tid < P_) ? g_att[b*P_ + tid] : -1e30f;
    red[tid] = v; __syncthreads();
    for (int s = 128; s > 0; s >>= 1){
        if (tid < s) red[tid] = fmaxf(red[tid], red[tid+s]);
        __syncthreads();
    }
    const float mx = red[0]; __syncthreads();
    const float e = (tid < P_) ? expf(v - mx) : 0.f;
    red[tid] = e; __syncthreads();
    for (int s = 128; s > 0; s >>= 1){
        if (tid < s) red[tid] += red[tid+s];
        __syncthreads();
    }
    const float inv = 1.f / red[0];
    if (tid < P_) alpha_out[b*P_ + tid] = e * inv;
}

// ---------------- kernel 4: awe[b,e] = sum_p enc[b,p,e] * alpha[b,p] ----------------
__global__ void __launch_bounds__(512)
awe_kernel(const float4* __restrict__ enc4, const float* __restrict__ alpha,
           float4* __restrict__ out4){
    const int b = blockIdx.x, tid = threadIdx.x;
    __shared__ float al[P_];
    if (tid < P_) al[tid] = alpha[b*P_ + tid];
    __syncthreads();
    float4 acc = make_float4(0.f, 0.f, 0.f, 0.f);
    const float4* ep = enc4 + (size_t)b * P_ * (E_/4) + tid;
    #pragma unroll 4
    for (int p = 0; p < P_; p++){
        const float a = al[p];
        const float4 v = ep[(size_t)p * (E_/4)];
        acc.x += a*v.x; acc.y += a*v.y; acc.z += a*v.z; acc.w += a*v.w;
    }
    out4[(size_t)b * (E_/4) + tid] = acc;
}

// ---------------- launch ----------------
extern "C" void kernel_launch(void* const* d_in, const int* in_sizes, int n_in,
                              void* d_out, int out_size){
    const float* enc  = (const float*)d_in[0];   // (B,P,E)
    const float* dh   = (const float*)d_in[1];   // (1,B,D)
    const float* We_w = (const float*)d_in[2];   // (E,A)
    const float* We_b = (const float*)d_in[3];   // (A)
    const float* Wd_w = (const float*)d_in[4];   // (D,A)
    const float* Wd_b = (const float*)d_in[5];   // (A)
    const float* Wf_w = (const float*)d_in[6];   // (A)
    // d_in[7] = Wf_b: scalar logit shift -> softmax-invariant, outputs don't depend on it.

    float* out       = (float*)d_out;
    float* awe_out   = out;                       // (B,E)
    float* alpha_out = out + (size_t)B_*E_;       // (B,P)

    cudaFuncSetAttribute(gemm_att_kernel, cudaFuncAttributeMaxDynamicSharedMemorySize, SMEM_BYTES);

    prep_bh       <<<dim3(E_/32, A_/32), dim3(32, 8)>>>(We_w);
    att2_kernel   <<<32, 128>>>(dh, Wd_w, Wd_b, We_b);
    gemm_att_kernel<<<(MTOT/MT)*2, 512, SMEM_BYTES>>>(enc, Wf_w);
    softmax_kernel<<<B_, 256>>>(alpha_out);
    awe_kernel    <<<B_, 512>>>((const float4*)enc, alpha_out, (float4*)awe_out);
}

// round 4
// speedup vs baseline: 1.4532x; 1.0536x over previous
#include <cuda_runtime.h>
#include <cuda_fp16.h>
#include <cstdint>
#include <cstddef>

#define B_    256
#define P_    196
#define E_    2048
#define A_    512
#define MTOT  (B_*P_)      // 50176

// GEMM tiling: 128x128 tile, 256 threads, 2 CTAs/SM
#define MT 128
#define NT 128
#define KC 64
#define NKC (E_/KC)        // 32
#define NSPLIT (A_/NT)     // 4

// scratch
__device__ float  g_att2[B_*A_];   // dh@Wd + Wd_b + We_b combined bias
__device__ float  g_att [MTOT];    // logits
__device__ __half g_Bth [A_*E_];   // We transposed to [N][K], fp16 (2MB)

// ---------------- helpers ----------------
__device__ __forceinline__ void cp_async16(void* smem_dst, const void* gmem_src){
    unsigned s = (unsigned)__cvta_generic_to_shared(smem_dst);
    asm volatile("cp.async.cg.shared.global [%0], [%1], 16;\n" :: "r"(s), "l"(gmem_src));
}
__device__ __forceinline__ uint32_t packh(float2 v){
    __half2 h = __float22half2_rn(v);
    return *reinterpret_cast<uint32_t*>(&h);
}
__device__ __forceinline__ void mma_fp16(float c[4], uint32_t a0, uint32_t a1, uint32_t a2, uint32_t a3,
                                         uint32_t b0, uint32_t b1){
    asm volatile(
        "mma.sync.aligned.m16n8k16.row.col.f32.f16.f16.f32 "
        "{%0,%1,%2,%3}, {%4,%5,%6,%7}, {%8,%9}, {%0,%1,%2,%3};\n"
        : "+f"(c[0]), "+f"(c[1]), "+f"(c[2]), "+f"(c[3])
        : "r"(a0), "r"(a1), "r"(a2), "r"(a3), "r"(b0), "r"(b1));
}

// ---------------- kernel 0: g_Bth[n][k] = fp16(We[k][n]) ----------------
__global__ void prep_bh(const float* __restrict__ We){
    __shared__ float t[32][33];
    const int k0 = blockIdx.x*32, n0 = blockIdx.y*32;
    const int tx = threadIdx.x, ty = threadIdx.y;   // (32,8)
    #pragma unroll
    for (int i = 0; i < 4; i++)
        t[ty + i*8][tx] = We[(size_t)(k0 + ty + i*8)*A_ + n0 + tx];
    __syncthreads();
    #pragma unroll
    for (int i = 0; i < 4; i++)
        g_Bth[(size_t)(n0 + ty + i*8)*E_ + k0 + tx] = __float2half_rn(t[tx][ty + i*8]);
}

// ---------------- kernel 1: att2/bias + zero logits ----------------
__global__ void att2_kernel(const float* __restrict__ dh,  const float* __restrict__ Wd,
                            const float* __restrict__ Wdb, const float* __restrict__ Web){
    __shared__ float dh_s[8][512];
    const int tid = threadIdx.x;
    const int bb  = blockIdx.x * 8;
    for (int i = tid; i < 8*512; i += 128)
        dh_s[i >> 9][i & 511] = dh[(size_t)bb*512 + i];
    for (int i = blockIdx.x*128 + tid; i < MTOT; i += 32*128)
        g_att[i] = 0.f;
    __syncthreads();

    float acc[8][4];
    #pragma unroll
    for (int j = 0; j < 4; j++){
        float base = Wdb[tid + j*128] + Web[tid + j*128];
        #pragma unroll
        for (int q = 0; q < 8; q++) acc[q][j] = base;
    }
    for (int k = 0; k < 512; k++){
        #pragma unroll
        for (int j = 0; j < 4; j++){
            float w = Wd[(size_t)k*512 + tid + j*128];
            #pragma unroll
            for (int q = 0; q < 8; q++) acc[q][j] += dh_s[q][k] * w;
        }
    }
    #pragma unroll
    for (int q = 0; q < 8; q++)
        #pragma unroll
        for (int j = 0; j < 4; j++)
            g_att2[(size_t)(bb+q)*512 + tid + j*128] = acc[q][j];
}

// ---------------- kernel 2: fused FP16 mma GEMM + relu + Wf-dot -> logits ----------------
// grid = (MTOT/MT)*NSPLIT = 392*4 = 1568, block 256, 2 CTAs/SM.
// m0 = (bid>>2)*128, n0 = (bid&3)*128.
// smem: As[2][128][68] f32 | Bs[2][128][72] half | bias[2][128] | wf[128] | satt[128]
#define AS_STRIDE 68
#define BS_STRIDE 72
#define AS_FLOATS (2*128*AS_STRIDE)                 // 17408
#define BS_HALVES (2*128*BS_STRIDE)                 // 18432
#define EX_FLOATS (256 + 128 + 128)
#define SMEM_BYTES (AS_FLOATS*4 + BS_HALVES*2 + EX_FLOATS*4)   // 108544

__device__ __forceinline__ void load_chunk(const float* __restrict__ enc,
                                           float* As, __half* Bs,
                                           int m0, int n0, int kc, int buf, int tid){
    const float* Ag = enc + (size_t)m0*E_ + kc*KC;
    float* Ab = As + buf*(128*AS_STRIDE);
    #pragma unroll
    for (int i = 0; i < 8; i++){
        int idx = tid + i*256;
        int r = idx >> 4, seg = idx & 15;                 // 128 rows x 16 float4
        cp_async16(Ab + r*AS_STRIDE + seg*4, Ag + (size_t)r*E_ + seg*4);
    }
    const __half* Bg = g_Bth + (size_t)n0*E_ + kc*KC;
    __half* Bb = Bs + buf*(128*BS_STRIDE);
    #pragma unroll
    for (int i = 0; i < 4; i++){
        int idx = tid + i*256;
        int n = idx >> 3, seg = idx & 7;                  // 128 rows x 8 chunks of 8 halves
        cp_async16(Bb + n*BS_STRIDE + seg*8, Bg + (size_t)n*E_ + seg*8);
    }
    asm volatile("cp.async.commit_group;\n");
}

__global__ void __launch_bounds__(256, 2)
gemm_att_kernel(const float* __restrict__ enc, const float* __restrict__ Wf){
    extern __shared__ char smraw[];
    float*  As     = (float*)smraw;
    __half* Bs     = (__half*)(smraw + AS_FLOATS*4);
    float*  bias_s = (float*)(smraw + AS_FLOATS*4 + BS_HALVES*2);   // [2][128]
    float*  wf_s   = bias_s + 256;
    float*  satt   = wf_s + 128;

    const int tid = threadIdx.x;
    const int bid = blockIdx.x;
    const int m0  = (bid >> 2) * MT;
    const int n0  = (bid & 3)  * NT;
    const int b_first = m0 / P_;

    {
        int j = tid >> 7, c = tid & 127;                  // 2 x 128
        int b = b_first + j;
        bias_s[tid] = (b < B_) ? g_att2[(size_t)b*A_ + n0 + c] : 0.f;
        if (tid < 128){ wf_s[tid] = Wf[n0 + tid]; satt[tid] = 0.f; }
    }

    const int warp = tid >> 5, lane = tid & 31;
    const int wm = warp >> 1, wn = warp & 1;        // 4x2 warp grid; warp tile 32x64
    const int g = lane >> 2, t = lane & 3;

    float c[2][8][4];
    #pragma unroll
    for (int mi = 0; mi < 2; mi++)
        #pragma unroll
        for (int ni = 0; ni < 8; ni++)
            #pragma unroll
            for (int j = 0; j < 4; j++) c[mi][ni][j] = 0.f;

    load_chunk(enc, As, Bs, m0, n0, 0, 0, tid);

    for (int kc = 0; kc < NKC; kc++){
        const int buf = kc & 1;
        if (kc < NKC-1){
            load_chunk(enc, As, Bs, m0, n0, kc+1, buf^1, tid);
            asm volatile("cp.async.wait_group 1;\n");
        } else {
            asm volatile("cp.async.wait_group 0;\n");
        }
        __syncthreads();

        const float*  Abase = As + buf*(128*AS_STRIDE) + (wm*32)*AS_STRIDE;
        const __half* Bbase = Bs + buf*(128*BS_STRIDE) + (wn*64)*BS_STRIDE;
        #pragma unroll
        for (int ks = 0; ks < 4; ks++){                  // 4 x k16
            uint32_t a[2][4];
            #pragma unroll
            for (int mi = 0; mi < 2; mi++){
                const float* ap = Abase + (mi*16 + g)*AS_STRIDE + ks*16 + 2*t;
                a[mi][0] = packh(*(const float2*)(ap));
                a[mi][1] = packh(*(const float2*)(ap + 8*AS_STRIDE));
                a[mi][2] = packh(*(const float2*)(ap + 8));
                a[mi][3] = packh(*(const float2*)(ap + 8*AS_STRIDE + 8));
            }
            #pragma unroll
            for (int ni = 0; ni < 8; ni++){
                const __half* bp = Bbase + (ni*8 + g)*BS_STRIDE + ks*16 + 2*t;
                uint32_t b0 = *(const uint32_t*)(bp);
                uint32_t b1 = *(const uint32_t*)(bp + 8);
                mma_fp16(c[0][ni], a[0][0], a[0][1], a[0][2], a[0][3], b0, b1);
                mma_fp16(c[1][ni], a[1][0], a[1][1], a[1][2], a[1][3], b0, b1);
            }
        }
        __syncthreads();
    }

    // epilogue: h = relu(acc + bias(b_row, col)); att += h .* Wf
    float attr[2][2] = {{0.f,0.f},{0.f,0.f}};
    #pragma unroll
    for (int ni = 0; ni < 8; ni++){
        const int cl = wn*64 + ni*8 + 2*t;               // local col
        const float w0 = wf_s[cl], w1 = wf_s[cl+1];
        #pragma unroll
        for (int mi = 0; mi < 2; mi++){
            #pragma unroll
            for (int rr = 0; rr < 2; rr++){
                const int rowg = m0 + wm*32 + mi*16 + g + rr*8;
                const int rb   = rowg / P_ - b_first;          // 0 or 1
                const float bv0 = bias_s[rb*128 + cl];
                const float bv1 = bias_s[rb*128 + cl + 1];
                const float h0 = fmaxf(c[mi][ni][rr*2+0] + bv0, 0.f);
                const float h1 = fmaxf(c[mi][ni][rr*2+1] + bv1, 0.f);
                attr[mi][rr] += h0*w0 + h1*w1;
            }
        }
    }
    #pragma unroll
    for (int mi = 0; mi < 2; mi++)
        #pragma unroll
        for (int rr = 0; rr < 2; rr++){
            float v = attr[mi][rr];
            v += __shfl_xor_sync(0xffffffffu, v, 1);
            v += __shfl_xor_sync(0xffffffffu, v, 2);
            if (t == 0) atomicAdd(&satt[wm*32 + mi*16 + g + rr*8], v);
        }
    __syncthreads();
    if (tid < 128) atomicAdd(&g_att[m0 + tid], satt[tid]);
}

// ---------------- kernel 3: softmax over P per batch row ----------------
__global__ void softmax_kernel(float* __restrict__ alpha_out){
    const int b = blockIdx.x, tid = threadIdx.x;    // 256 threads
    __shared__ float red[256];
    float v = (tid < P_) ? g_att[b*P_ + tid] : -1e30f;
    red[tid] = v; __syncthreads();
    for (int s = 128; s > 0; s >>= 1){
        if (tid < s) red[tid] = fmaxf(red[tid], red[tid+s]);
        __syncthreads();
    }
    const float mx = red[0]; __syncthreads();
    const float e = (tid < P_) ? expf(v - mx) : 0.f;
    red[tid] = e; __syncthreads();
    for (int s = 128; s > 0; s >>= 1){
        if (tid < s) red[tid] += red[tid+s];
        __syncthreads();
    }
    const float inv = 1.f / red[0];
    if (tid < P_) alpha_out[b*P_ + tid] = e * inv;
}

// ---------------- kernel 4: awe[b,e] = sum_p enc[b,p,e] * alpha[b,p] ----------------
__global__ void __launch_bounds__(512)
awe_kernel(const float4* __restrict__ enc4, const float* __restrict__ alpha,
           float4* __restrict__ out4){
    const int b = blockIdx.x, tid = threadIdx.x;
    __shared__ float al[P_];
    if (tid < P_) al[tid] = alpha[b*P_ + tid];
    __syncthreads();
    float4 acc = make_float4(0.f, 0.f, 0.f, 0.f);
    const float4* ep = enc4 + (size_t)b * P_ * (E_/4) + tid;
    #pragma unroll 4
    for (int p = 0; p < P_; p++){
        const float a = al[p];
        const float4 v = ep[(size_t)p * (E_/4)];
        acc.x += a*v.x; acc.y += a*v.y; acc.z += a*v.z; acc.w += a*v.w;
    }
    out4[(size_t)b * (E_/4) + tid] = acc;
}

// ---------------- launch ----------------
extern "C" void kernel_launch(void* const* d_in, const int* in_sizes, int n_in,
                              void* d_out, int out_size){
    const float* enc  = (const float*)d_in[0];   // (B,P,E)
    const float* dh   = (const float*)d_in[1];   // (1,B,D)
    const float* We_w = (const float*)d_in[2];   // (E,A)
    const float* We_b = (const float*)d_in[3];   // (A)
    const float* Wd_w = (const float*)d_in[4];   // (D,A)
    const float* Wd_b = (const float*)d_in[5];   // (A)
    const float* Wf_w = (const float*)d_in[6];   // (A)
    // d_in[7] = Wf_b: scalar logit shift -> softmax-invariant, outputs don't depend on it.

    float* out       = (float*)d_out;
    float* awe_out   = out;                       // (B,E)
    float* alpha_out = out + (size_t)B_*E_;       // (B,P)

    cudaFuncSetAttribute(gemm_att_kernel, cudaFuncAttributeMaxDynamicSharedMemorySize, SMEM_BYTES);

    prep_bh       <<<dim3(E_/32, A_/32), dim3(32, 8)>>>(We_w);
    att2_kernel   <<<32, 128>>>(dh, Wd_w, Wd_b, We_b);
    gemm_att_kernel<<<(MTOT/MT)*NSPLIT, 256, SMEM_BYTES>>>(enc, Wf_w);
    softmax_kernel<<<B_, 256>>>(alpha_out);
    awe_kernel    <<<B_, 512>>>((const float4*)enc, alpha_out, (float4*)awe_out);
}

// round 6
// speedup vs baseline: 1.4600x; 1.0047x over previous
#include <cuda_runtime.h>
#include <cuda_fp16.h>
#include <cstdint>
#include <cstddef>

#define B_    256
#define P_    196
#define E_    2048
#define A_    512
#define MTOT  (B_*P_)      // 50176

// GEMM tiling: 128x128 tile, 256 threads, 2 CTAs/SM
#define MT 128
#define NT 128
#define KC 32
#define NKC (E_/KC)        // 64
#define NSPLIT (A_/NT)     // 4
#define STRIDE 40          // halves per smem row (80B -> conflict-free ldmatrix)

// scratch
__device__ float  g_att2[B_*A_];   // dh@Wd + Wd_b + We_b combined bias
__device__ float  g_att [MTOT];    // logits
__device__ __half g_Bth [A_*E_];   // We transposed to [N][K], fp16 (2MB)

// ---------------- helpers ----------------
__device__ __forceinline__ void cp_async16(void* smem_dst, const void* gmem_src){
    unsigned s = (unsigned)__cvta_generic_to_shared(smem_dst);
    asm volatile("cp.async.cg.shared.global [%0], [%1], 16;\n" :: "r"(s), "l"(gmem_src));
}
__device__ __forceinline__ uint32_t packh(float a, float b){
    __half2 h = __floats2half2_rn(a, b);
    return *reinterpret_cast<uint32_t*>(&h);
}
__device__ __forceinline__ void mma_fp16(float c[4], const uint32_t a[4], uint32_t b0, uint32_t b1){
    asm volatile(
        "mma.sync.aligned.m16n8k16.row.col.f32.f16.f16.f32 "
        "{%0,%1,%2,%3}, {%4,%5,%6,%7}, {%8,%9}, {%0,%1,%2,%3};\n"
        : "+f"(c[0]), "+f"(c[1]), "+f"(c[2]), "+f"(c[3])
        : "r"(a[0]), "r"(a[1]), "r"(a[2]), "r"(a[3]), "r"(b0), "r"(b1));
}
__device__ __forceinline__ void ldsm_x4(uint32_t r[4], uint32_t saddr){
    asm volatile("ldmatrix.sync.aligned.m8n8.x4.shared.b16 {%0,%1,%2,%3}, [%4];"
        : "=r"(r[0]), "=r"(r[1]), "=r"(r[2]), "=r"(r[3]) : "r"(saddr));
}
__device__ __forceinline__ uint32_t smem_u32(const void* p){
    return (uint32_t)__cvta_generic_to_shared(p);
}

// ---------------- kernel 0: g_Bth[n][k] = fp16(We[k][n]) ----------------
__global__ void prep_bh(const float* __restrict__ We){
    __shared__ float t[32][33];
    const int k0 = blockIdx.x*32, n0 = blockIdx.y*32;
    const int tx = threadIdx.x, ty = threadIdx.y;   // (32,8)
    #pragma unroll
    for (int i = 0; i < 4; i++)
        t[ty + i*8][tx] = We[(size_t)(k0 + ty + i*8)*A_ + n0 + tx];
    __syncthreads();
    #pragma unroll
    for (int i = 0; i < 4; i++)
        g_Bth[(size_t)(n0 + ty + i*8)*E_ + k0 + tx] = __float2half_rn(t[tx][ty + i*8]);
}

// ---------------- kernel 1: att2/bias + zero logits ----------------
__global__ void att2_kernel(const float* __restrict__ dh,  const float* __restrict__ Wd,
                            const float* __restrict__ Wdb, const float* __restrict__ Web){
    __shared__ float dh_s[8][512];
    const int tid = threadIdx.x;
    const int bb  = blockIdx.x * 8;
    for (int i = tid; i < 8*512; i += 128)
        dh_s[i >> 9][i & 511] = dh[(size_t)bb*512 + i];
    for (int i = blockIdx.x*128 + tid; i < MTOT; i += 32*128)
        g_att[i] = 0.f;
    __syncthreads();

    float acc[8][4];
    #pragma unroll
    for (int j = 0; j < 4; j++){
        float base = Wdb[tid + j*128] + Web[tid + j*128];
        #pragma unroll
        for (int q = 0; q < 8; q++) acc[q][j] = base;
    }
    for (int k = 0; k < 512; k++){
        #pragma unroll
        for (int j = 0; j < 4; j++){
            float w = Wd[(size_t)k*512 + tid + j*128];
            #pragma unroll
            for (int q = 0; q < 8; q++) acc[q][j] += dh_s[q][k] * w;
        }
    }
    #pragma unroll
    for (int q = 0; q < 8; q++)
        #pragma unroll
        for (int j = 0; j < 4; j++)
            g_att2[(size_t)(bb+q)*512 + tid + j*128] = acc[q][j];
}

// ---------------- kernel 2: fused FP16 mma GEMM + relu + Wf-dot -> logits ----------------
// grid = 392*4 = 1568, block 256, 2 CTAs/SM.
// smem: As[2][128][40] half | Bs[2][128][40] half | bias[2][128] | wf[128] | satt[128]
#define STAGE_H (128*STRIDE)                         // 5120 halves
#define AS_H    (2*STAGE_H)
#define BS_H    (2*STAGE_H)
#define EX_FLOATS (256 + 128 + 128)
#define SMEM_BYTES ((AS_H + BS_H)*2 + EX_FLOATS*4)   // 43008

__global__ void __launch_bounds__(256, 2)
gemm_att_kernel(const float* __restrict__ enc, const float* __restrict__ Wf){
    extern __shared__ char smraw[];
    __half* As     = (__half*)smraw;
    __half* Bs     = As + AS_H;
    float*  bias_s = (float*)(smraw + (AS_H + BS_H)*2);   // [2][128]
    float*  wf_s   = bias_s + 256;
    float*  satt   = wf_s + 128;

    const int tid = threadIdx.x;
    const int bid = blockIdx.x;
    const int m0  = (bid >> 2) * MT;
    const int n0  = (bid & 3)  * NT;
    const int b_first = m0 / P_;

    {
        int j = tid >> 7, c2 = tid & 127;                 // 2 x 128
        int b = b_first + j;
        bias_s[tid] = (b < B_) ? g_att2[(size_t)b*A_ + n0 + c2] : 0.f;
        if (tid < 128){ wf_s[tid] = Wf[n0 + tid]; satt[tid] = 0.f; }
    }

    const int warp = tid >> 5, lane = tid & 31;
    const int wm = warp >> 1, wn = warp & 1;        // 4x2 warp grid; warp tile 32x64
    const int g = lane >> 2, t = lane & 3;

    const uint32_t as_base = smem_u32(As);
    const uint32_t bs_base = smem_u32(Bs);

    // ldmatrix lane addressing (halves)
    const int a_row  = lane & 15;
    const int a_koff = (lane >> 4) * 8;
    const int b_row  = (lane & 7) + ((lane >> 4) & 1) * 8;
    const int b_koff = ((lane >> 3) & 1) * 8;

    // A staging: thread covers row = tid>>1 (all 128 rows), kseg = tid&1 (16 floats)
    const int st_row  = tid >> 1;
    const int st_kseg = tid & 1;
    const float4* Ag = (const float4*)(enc + (size_t)(m0 + st_row)*E_) + st_kseg*4;
    __half* AsW = As + st_row*STRIDE + st_kseg*16;

    // B staging via cp.async: idx -> n = idx>>2, seg = idx&3 (16B each)
    const __half* Bg = g_Bth + (size_t)n0*E_;

    float c[2][8][4];
    #pragma unroll
    for (int mi = 0; mi < 2; mi++)
        #pragma unroll
        for (int ni = 0; ni < 8; ni++)
            #pragma unroll
            for (int j = 0; j < 4; j++) c[mi][ni][j] = 0.f;

    // ---- prologue: stage chunk 0 ----
    {
        float4 v[4];
        #pragma unroll
        for (int j = 0; j < 4; j++) v[j] = Ag[j];          // kc=0
        uint32_t* w = (uint32_t*)AsW;
        #pragma unroll
        for (int j = 0; j < 4; j++){
            w[j*2+0] = packh(v[j].x, v[j].y);
            w[j*2+1] = packh(v[j].z, v[j].w);
        }
        #pragma unroll
        for (int i = 0; i < 2; i++){
            int idx = tid + i*256;
            int n = idx >> 2, seg = idx & 3;
            cp_async16(Bs + n*STRIDE + seg*8, Bg + (size_t)n*E_ + seg*8);
        }
        asm volatile("cp.async.commit_group;\n");
    }

    for (int kc = 0; kc < NKC; kc++){
        const int buf = kc & 1;
        const uint32_t a_cta = as_base + (uint32_t)buf*STAGE_H*2;
        const uint32_t b_cta = bs_base + (uint32_t)buf*STAGE_H*2;
        __half* AsN = As + (buf^1)*STAGE_H;
        __half* BsN = Bs + (buf^1)*STAGE_H;

        float4 v[4];
        const bool pref = (kc + 1 < NKC);
        if (pref){
            // B chunk kc+1
            #pragma unroll
            for (int i = 0; i < 2; i++){
                int idx = tid + i*256;
                int n = idx >> 2, seg = idx & 3;
                cp_async16(BsN + n*STRIDE + seg*8, Bg + (size_t)n*E_ + (kc+1)*KC + seg*8);
            }
            asm volatile("cp.async.commit_group;\n");
            // A chunk kc+1 -> regs (covers ALL 128 rows: 2 threads per row)
            #pragma unroll
            for (int j = 0; j < 4; j++) v[j] = Ag[(size_t)(kc+1)*(KC/4) + j];
        }

        if (pref) asm volatile("cp.async.wait_group 1;\n");
        else      asm volatile("cp.async.wait_group 0;\n");
        __syncthreads();

        // fragment base addresses (bytes)
        const uint32_t a_base = a_cta + (uint32_t)(((wm*32 + a_row)*STRIDE + a_koff) * 2);
        const uint32_t b_base = b_cta + (uint32_t)(((wn*64 + b_row)*STRIDE + b_koff) * 2);

        #pragma unroll
        for (int ks = 0; ks < 2; ks++){
            uint32_t a[2][4], b[4][4];
            #pragma unroll
            for (int mi = 0; mi < 2; mi++)
                ldsm_x4(a[mi], a_base + (uint32_t)((mi*16*STRIDE + ks*16) * 2));
            #pragma unroll
            for (int p = 0; p < 4; p++)
                ldsm_x4(b[p], b_base + (uint32_t)((p*16*STRIDE + ks*16) * 2));
            #pragma unroll
            for (int p = 0; p < 4; p++){
                mma_fp16(c[0][2*p+0], a[0], b[p][0], b[p][1]);
                mma_fp16(c[1][2*p+0], a[1], b[p][0], b[p][1]);
                mma_fp16(c[0][2*p+1], a[0], b[p][2], b[p][3]);
                mma_fp16(c[1][2*p+1], a[1], b[p][2], b[p][3]);
            }
        }

        if (pref){
            // convert + store A chunk kc+1 into buf^1
            uint32_t* w = (uint32_t*)(AsN + st_row*STRIDE + st_kseg*16);
            #pragma unroll
            for (int j = 0; j < 4; j++){
                w[j*2+0] = packh(v[j].x, v[j].y);
                w[j*2+1] = packh(v[j].z, v[j].w);
            }
        }
        __syncthreads();
    }

    // epilogue: h = relu(acc + bias(b_row, col)); att += h .* Wf
    float attr[2][2] = {{0.f,0.f},{0.f,0.f}};
    #pragma unroll
    for (int ni = 0; ni < 8; ni++){
        const int cl = wn*64 + ni*8 + 2*t;               // local col
        const float w0 = wf_s[cl], w1 = wf_s[cl+1];
        #pragma unroll
        for (int mi = 0; mi < 2; mi++){
            #pragma unroll
            for (int rr = 0; rr < 2; rr++){
                const int rowg = m0 + wm*32 + mi*16 + g + rr*8;
                const int rb   = rowg / P_ - b_first;          // 0 or 1
                const float bv0 = bias_s[rb*128 + cl];
                const float bv1 = bias_s[rb*128 + cl + 1];
                const float h0 = fmaxf(c[mi][ni][rr*2+0] + bv0, 0.f);
                const float h1 = fmaxf(c[mi][ni][rr*2+1] + bv1, 0.f);
                attr[mi][rr] += h0*w0 + h1*w1;
            }
        }
    }
    #pragma unroll
    for (int mi = 0; mi < 2; mi++)
        #pragma unroll
        for (int rr = 0; rr < 2; rr++){
            float v = attr[mi][rr];
            v += __shfl_xor_sync(0xffffffffu, v, 1);
            v += __shfl_xor_sync(0xffffffffu, v, 2);
            if (t == 0) atomicAdd(&satt[wm*32 + mi*16 + g + rr*8], v);
        }
    __syncthreads();
    if (tid < 128) atomicAdd(&g_att[m0 + tid], satt[tid]);
}

// ---------------- kernel 3: softmax over P per batch row ----------------
__global__ void softmax_kernel(float* __restrict__ alpha_out){
    const int b = blockIdx.x, tid = threadIdx.x;    // 256 threads
    __shared__ float red[256];
    float v = (tid < P_) ? g_att[b*P_ + tid] : -1e30f;
    red[tid] = v; __syncthreads();
    for (int s = 128; s > 0; s >>= 1){
        if (tid < s) red[tid] = fmaxf(red[tid], red[tid+s]);
        __syncthreads();
    }
    const float mx = red[0]; __syncthreads();
    const float e = (tid < P_) ? expf(v - mx) : 0.f;
    red[tid] = e; __syncthreads();
    for (int s = 128; s > 0; s >>= 1){
        if (tid < s) red[tid] += red[tid+s];
        __syncthreads();
    }
    const float inv = 1.f / red[0];
    if (tid < P_) alpha_out[b*P_ + tid] = e * inv;
}

// ---------------- kernel 4: awe[b,e] = sum_p enc[b,p,e] * alpha[b,p] ----------------
__global__ void __launch_bounds__(512)
awe_kernel(const float4* __restrict__ enc4, const float* __restrict__ alpha,
           float4* __restrict__ out4){
    const int b = blockIdx.x, tid = threadIdx.x;
    __shared__ float al[P_];
    if (tid < P_) al[tid] = alpha[b*P_ + tid];
    __syncthreads();
    float4 acc = make_float4(0.f, 0.f, 0.f, 0.f);
    const float4* ep = enc4 + (size_t)b * P_ * (E_/4) + tid;
    #pragma unroll 4
    for (int p = 0; p < P_; p++){
        const float a = al[p];
        const float4 v = ep[(size_t)p * (E_/4)];
        acc.x += a*v.x; acc.y += a*v.y; acc.z += a*v.z; acc.w += a*v.w;
    }
    out4[(size_t)b * (E_/4) + tid] = acc;
}

// ---------------- launch ----------------
extern "C" void kernel_launch(void* const* d_in, const int* in_sizes, int n_in,
                              void* d_out, int out_size){
    const float* enc  = (const float*)d_in[0];   // (B,P,E)
    const float* dh   = (const float*)d_in[1];   // (1,B,D)
    const float* We_w = (const float*)d_in[2];   // (E,A)
    const float* We_b = (const float*)d_in[3];   // (A)
    const float* Wd_w = (const float*)d_in[4];   // (D,A)
    const float* Wd_b = (const float*)d_in[5];   // (A)
    const float* Wf_w = (const float*)d_in[6];   // (A)
    // d_in[7] = Wf_b: scalar logit shift -> softmax-invariant, outputs don't depend on it.

    float* out       = (float*)d_out;
    float* awe_out   = out;                       // (B,E)
    float* alpha_out = out + (size_t)B_*E_;       // (B,P)

    cudaFuncSetAttribute(gemm_att_kernel, cudaFuncAttributeMaxDynamicSharedMemorySize, SMEM_BYTES);

    prep_bh       <<<dim3(E_/32, A_/32), dim3(32, 8)>>>(We_w);
    att2_kernel   <<<32, 128>>>(dh, Wd_w, Wd_b, We_b);
    gemm_att_kernel<<<(MTOT/MT)*NSPLIT, 256, SMEM_BYTES>>>(enc, Wf_w);
    softmax_kernel<<<B_, 256>>>(alpha_out);
    awe_kernel    <<<B_, 512>>>((const float4*)enc, alpha_out, (float4*)awe_out);
}